// round 8
// baseline (speedup 1.0000x reference)
#include <cuda_runtime.h>
#include <stdint.h>

// Problem constants (fixed by dataset)
#define S_TOK   16384
#define C_DIM   1280
#define C3      3840
#define D_HEAD  80
#define BLK     16
#define NBLK    (S_TOK / BLK)   // 1024

// Scratch (__device__ globals; no allocation allowed)
__device__ float    g_qkv[(size_t)S_TOK * C3];        // permuted-order QKV (fp32)
__device__ uint32_t g_y  [(size_t)S_TOK * C_DIM];     // attention out (tf32 bits), ORIGINAL order
__device__ uint32_t g_xt [(size_t)S_TOK * C_DIM];     // x as tf32 bits
__device__ uint32_t g_wqkvT32 [(size_t)C_DIM * C3];   // W_qkv  [K,N] tf32 bits
__device__ uint32_t g_wprojT32[(size_t)C_DIM * C_DIM];// W_proj [K,N] tf32 bits

// ---------------------------------------------------------------------------
__device__ __forceinline__ uint32_t f2tf(float f) {
    uint32_t r; asm("cvt.rna.tf32.f32 %0, %1;" : "=r"(r) : "f"(f)); return r;
}
__device__ __forceinline__ uint32_t smem_u32(const void* p) {
    uint32_t a;
    asm("{ .reg .u64 t; cvta.to.shared.u64 t, %1; cvt.u32.u64 %0, t; }" : "=r"(a) : "l"(p));
    return a;
}
__device__ __forceinline__ void cpa16(uint32_t dst, const void* src) {
    asm volatile("cp.async.cg.shared.global [%0], [%1], 16;" :: "r"(dst), "l"(src) : "memory");
}
__device__ __forceinline__ void cpa_commit() {
    asm volatile("cp.async.commit_group;" ::: "memory");
}
__device__ __forceinline__ void cpa_wait1() {
    asm volatile("cp.async.wait_group 1;" ::: "memory");
}

__device__ __forceinline__ void mma_tf32(float* d, const uint32_t* a, const uint32_t* b) {
    asm volatile(
        "mma.sync.aligned.m16n8k8.row.col.f32.tf32.tf32.f32 "
        "{%0,%1,%2,%3}, {%4,%5,%6,%7}, {%8,%9}, {%0,%1,%2,%3};"
        : "+f"(d[0]), "+f"(d[1]), "+f"(d[2]), "+f"(d[3])
        : "r"(a[0]), "r"(a[1]), "r"(a[2]), "r"(a[3]),
          "r"(b[0]), "r"(b[1]));
}

// ---------------------------------------------------------------------------
// TF32 mma.sync GEMM, CTA tile 128x128, BK=32, 256 thr (8 warps as 2x4),
// warp tile 64x32 (mt=4, nt=4). 3-stage cp.async pipeline, 1 sync/iter.
// 2 CTAs/SM => 16 warps/SM (4 per SMSP) for TLP latency hiding.
// A: tf32 bits [M,K] (optional row gather). B: tf32 bits [K,N]. C: fp32.
// smem/stage: A [128][36]u32 = 18432B ; B [32][136]u32 = 17408B -> 35840B
// ---------------------------------------------------------------------------
#define BM 128
#define BN 128
#define BK 32
#define ASTR 36      // A [m][k] stride (words): frag banks 4g+t, all distinct
#define BSTR 136     // B [k][n] stride (words): frag banks 8t+g, all distinct
#define ST_A_BYTES (BM * ASTR * 4)               // 18432
#define ST_BYTES   (ST_A_BYTES + BK * BSTR * 4)  // 35840
#define NSTAGE 3
#define SMEM_BYTES (NSTAGE * ST_BYTES)           // 107520

template<bool GATHER>
__global__ __launch_bounds__(256, 2)
void mma_gemm32(const uint32_t* __restrict__ A, const uint32_t* __restrict__ B,
                float* __restrict__ C, const int* __restrict__ gidx,
                int N, int K)
{
    extern __shared__ char smem[];
    const uint32_t sb = smem_u32(smem);

    const int tid  = threadIdx.x;
    const int bx   = blockIdx.x, by = blockIdx.y;
    const int warp = tid >> 5, lane = tid & 31;
    const int wm   = warp >> 2, wn = warp & 3;   // 2 x 4 warp grid
    const int g    = lane >> 2, t = lane & 3;

    // ---- producer mapping (256 threads, 8 cpa16 / thread / stage) ----
    // A: row arow = tid>>1 (0..127), 4 contiguous 16B chunks at half achk4
    const int arow  = tid >> 1;
    const int achk4 = (tid & 1) * 4;      // chunk group: 0 or 4 (64B half-row)
    int gm = by * BM + arow;
    if (GATHER) gm = gidx[gm];
    const uint32_t* Asrc = A + (size_t)gm * K + achk4 * 4;
    const uint32_t  a_dst = arow * (ASTR * 4) + achk4 * 16;
    // B: k-row brow = tid>>3 (0..31), 4 chunks at (tid&7) + 8j
    const int brow = tid >> 3;
    const int bch  = tid & 7;
    const uint32_t* Bsrc = B + (size_t)brow * N + bx * BN + bch * 4;
    const uint32_t  b_dst = ST_A_BYTES + brow * (BSTR * 4) + bch * 16;

    float acc[4][4][4];
    #pragma unroll
    for (int mt = 0; mt < 4; mt++)
        #pragma unroll
        for (int nt = 0; nt < 4; nt++)
            #pragma unroll
            for (int i = 0; i < 4; i++) acc[mt][nt][i] = 0.f;

    const int NIT = K / BK;   // 40

    // ---- prologue: issue stages 0,1 ----
    #pragma unroll
    for (int s = 0; s < NSTAGE - 1; s++) {
        const uint32_t so = sb + s * ST_BYTES;
        const int kt = s * BK;
        #pragma unroll
        for (int j = 0; j < 4; j++)
            cpa16(so + a_dst + j * 16, Asrc + kt + j * 4);
        #pragma unroll
        for (int j = 0; j < 4; j++)
            cpa16(so + b_dst + j * 128, Bsrc + (size_t)kt * N + j * 32);
        cpa_commit();
    }

    int stage = 0;
    for (int i = 0; i < NIT; i++) {
        cpa_wait1();          // group i complete -> stage i%3 ready
        __syncthreads();      // + all reads of stage (i-1)%3 finished

        // issue tile i+2 into stage (i+2)%3 == (i-1)%3
        if (i + NSTAGE - 1 < NIT) {
            int s2 = stage + (NSTAGE - 1);
            if (s2 >= NSTAGE) s2 -= NSTAGE;
            const uint32_t so = sb + s2 * ST_BYTES;
            const int kt = (i + NSTAGE - 1) * BK;
            #pragma unroll
            for (int j = 0; j < 4; j++)
                cpa16(so + a_dst + j * 16, Asrc + kt + j * 4);
            #pragma unroll
            for (int j = 0; j < 4; j++)
                cpa16(so + b_dst + j * 128, Bsrc + (size_t)kt * N + j * 32);
        }
        cpa_commit();

        // ---- compute on current stage: 4 k8 steps ----
        const uint32_t* As = (const uint32_t*)(smem + stage * ST_BYTES);
        const uint32_t* Bs = (const uint32_t*)(smem + stage * ST_BYTES + ST_A_BYTES);

        #pragma unroll
        for (int s8 = 0; s8 < 4; s8++) {
            const int ks = s8 * 8;
            uint32_t af[4][4];
            #pragma unroll
            for (int mt = 0; mt < 4; mt++) {
                const int m0 = wm * 64 + mt * 16 + g;
                af[mt][0] = As[m0 * ASTR + ks + t];
                af[mt][1] = As[(m0 + 8) * ASTR + ks + t];
                af[mt][2] = As[m0 * ASTR + ks + t + 4];
                af[mt][3] = As[(m0 + 8) * ASTR + ks + t + 4];
            }
            uint32_t bf[4][2];
            #pragma unroll
            for (int nt = 0; nt < 4; nt++) {
                const int n = wn * 32 + nt * 8 + g;
                bf[nt][0] = Bs[(ks + t) * BSTR + n];
                bf[nt][1] = Bs[(ks + t + 4) * BSTR + n];
            }
            #pragma unroll
            for (int mt = 0; mt < 4; mt++)
                #pragma unroll
                for (int nt = 0; nt < 4; nt++)
                    mma_tf32(acc[mt][nt], af[mt], bf[nt]);
        }

        stage = (stage + 1 == NSTAGE) ? 0 : stage + 1;
    }

    // ---- epilogue ----
    #pragma unroll
    for (int mt = 0; mt < 4; mt++) {
        const int row0 = by * BM + wm * 64 + mt * 16 + g;
        #pragma unroll
        for (int nt = 0; nt < 4; nt++) {
            const int col = bx * BN + wn * 32 + nt * 8 + t * 2;
            *(float2*)(C + (size_t)row0 * N + col) =
                make_float2(acc[mt][nt][0], acc[mt][nt][1]);
            *(float2*)(C + (size_t)(row0 + 8) * N + col) =
                make_float2(acc[mt][nt][2], acc[mt][nt][3]);
        }
    }
}

// ---------------------------------------------------------------------------
// Elementwise fp32 -> tf32 bits
// ---------------------------------------------------------------------------
__global__ void cvt_tf32_kernel(const float* __restrict__ in,
                                uint32_t* __restrict__ out, long n)
{
    long i = ((long)blockIdx.x * blockDim.x + threadIdx.x) * 4;
    if (i >= n) return;
    float4 f = *(const float4*)(in + i);
    uint4 u = make_uint4(f2tf(f.x), f2tf(f.y), f2tf(f.z), f2tf(f.w));
    *(uint4*)(out + i) = u;
}

// ---------------------------------------------------------------------------
// Windowed attention, RoPE fused on load, inverse-permutation scatter.
// Writes y as tf32 bits (feeds GEMM2 A directly).
// ---------------------------------------------------------------------------
__global__ __launch_bounds__(256)
void attn_kernel(const float* __restrict__ qkv, uint32_t* __restrict__ y,
                 const int* __restrict__ win,
                 const float* __restrict__ cosp, const float* __restrict__ sinp)
{
    const int b = blockIdx.x >> 4;
    const int h = blockIdx.x & 15;

    __shared__ float qs[BLK][D_HEAD + 1];
    __shared__ float ks[BLK][D_HEAD + 1];
    __shared__ float vs[BLK][D_HEAD + 1];
    __shared__ float att[BLK][BLK + 1];
    __shared__ int   toks[BLK];

    const int tid = threadIdx.x;
    if (tid < BLK) toks[tid] = win[b * BLK + tid];
    __syncthreads();

    for (int tdx = tid; tdx < BLK * D_HEAD; tdx += 256) {
        int i = tdx / D_HEAD, d = tdx % D_HEAD;
        size_t base = (size_t)(b * BLK + i) * C3 + (size_t)h * D_HEAD + d;
        float q = qkv[base];
        float k = qkv[base + C_DIM];
        float v = qkv[base + 2 * C_DIM];
        int tok = toks[i];
        float cv = cosp[(size_t)tok * D_HEAD + d];
        float sv = sinp[(size_t)tok * D_HEAD + d];
        qs[i][d] = q * cv + k * sv;
        ks[i][d] = k * cv - q * sv;
        vs[i][d] = v;
    }
    __syncthreads();

    {
        int i = tid >> 4, j = tid & 15;
        float sc = 0.f;
        #pragma unroll
        for (int d = 0; d < D_HEAD; d++) sc += qs[i][d] * ks[j][d];
        att[i][j] = sc * 0.11180339887498949f;   // 1/sqrt(80)
    }
    __syncthreads();

    if (tid < BLK) {
        float m = -1e30f;
        #pragma unroll
        for (int j = 0; j < BLK; j++) m = fmaxf(m, att[tid][j]);
        float sum = 0.f;
        #pragma unroll
        for (int j = 0; j < BLK; j++) {
            float e = __expf(att[tid][j] - m);
            att[tid][j] = e;
            sum += e;
        }
        float inv = 1.f / sum;
        #pragma unroll
        for (int j = 0; j < BLK; j++) att[tid][j] *= inv;
    }
    __syncthreads();

    for (int tdx = tid; tdx < BLK * D_HEAD; tdx += 256) {
        int i = tdx / D_HEAD, d = tdx % D_HEAD;
        float a = 0.f;
        #pragma unroll
        for (int j = 0; j < BLK; j++) a += att[i][j] * vs[j][d];
        y[(size_t)toks[i] * C_DIM + (size_t)h * D_HEAD + d] = f2tf(a);
    }
}

// ---------------------------------------------------------------------------
extern "C" void kernel_launch(void* const* d_in, const int* in_sizes, int n_in,
                              void* d_out, int out_size)
{
    const float* x     = (const float*)d_in[0];
    const float* cosp  = (const float*)d_in[1];
    const float* sinp  = (const float*)d_in[2];
    const float* Wqkv  = (const float*)d_in[3];
    const float* Wproj = (const float*)d_in[4];
    const int*   win   = (const int*)  d_in[5];
    float* out = (float*)d_out;

    float *qkv_ptr;
    uint32_t *y_ptr, *xt_ptr, *wqkv_ptr, *wproj_ptr;
    cudaGetSymbolAddress((void**)&qkv_ptr,   g_qkv);
    cudaGetSymbolAddress((void**)&y_ptr,     g_y);
    cudaGetSymbolAddress((void**)&xt_ptr,    g_xt);
    cudaGetSymbolAddress((void**)&wqkv_ptr,  g_wqkvT32);
    cudaGetSymbolAddress((void**)&wproj_ptr, g_wprojT32);

    cudaFuncSetAttribute(mma_gemm32<true>,
        cudaFuncAttributeMaxDynamicSharedMemorySize, SMEM_BYTES);
    cudaFuncSetAttribute(mma_gemm32<false>,
        cudaFuncAttributeMaxDynamicSharedMemorySize, SMEM_BYTES);

    // 0) pre-convert x and weights to tf32 bits
    {
        long nx = (long)S_TOK * C_DIM;
        cvt_tf32_kernel<<<(int)(nx / 4 / 256), 256>>>(x, xt_ptr, nx);
        long nw1 = (long)C_DIM * C3;
        cvt_tf32_kernel<<<(int)(nw1 / 4 / 256), 256>>>(Wqkv, wqkv_ptr, nw1);
        long nw2 = (long)C_DIM * C_DIM;
        cvt_tf32_kernel<<<(int)(nw2 / 4 / 256), 256>>>(Wproj, wproj_ptr, nw2);
    }

    // 1) QKV GEMM (fused gather): g_qkv[s] = x[win[s]] @ W_qkv
    {
        dim3 grid(C3 / BN, S_TOK / BM);   // 30 x 128
        mma_gemm32<true><<<grid, 256, SMEM_BYTES>>>(xt_ptr, wqkv_ptr, qkv_ptr,
                                                    win, C3, C_DIM);
    }

    // 2) Windowed attention (RoPE fused) + inverse scatter, tf32 output
    attn_kernel<<<NBLK * 16, 256>>>(qkv_ptr, y_ptr, win, cosp, sinp);

    // 3) Output projection: out = g_y @ W_proj
    {
        dim3 grid(C_DIM / BN, S_TOK / BM);  // 10 x 128
        mma_gemm32<false><<<grid, 256, SMEM_BYTES>>>(y_ptr, wproj_ptr, out,
                                                     nullptr, C_DIM, C_DIM);
    }
}

// round 9
// speedup vs baseline: 1.2028x; 1.2028x over previous
#include <cuda_runtime.h>
#include <stdint.h>

// Problem constants (fixed by dataset)
#define S_TOK   16384
#define C_DIM   1280
#define C3      3840
#define D_HEAD  80
#define BLK     16
#define NBLK    (S_TOK / BLK)   // 1024
#define KDIM    1280
#define KB8     (KDIM / 8)      // 160

// Scratch (__device__ globals; no allocation allowed)
__device__ float    g_qkv[(size_t)S_TOK * C3];          // permuted-order QKV (fp32, row-major)
__device__ uint32_t g_xt [(size_t)S_TOK * KDIM];        // x gathered+tf32, A-frag layout
__device__ uint32_t g_y  [(size_t)S_TOK * KDIM];        // attn out tf32, A-frag layout (orig order)
__device__ uint32_t g_wqkvF [(size_t)(C3   / 64) * KB8 * 832]; // W_qkv  B-frag layout
__device__ uint32_t g_wprojF[(size_t)(C_DIM / 64) * KB8 * 832]; // W_proj B-frag layout

// ---------------------------------------------------------------------------
__device__ __forceinline__ uint32_t f2tf(float f) {
    uint32_t r; asm("cvt.rna.tf32.f32 %0, %1;" : "=r"(r) : "f"(f)); return r;
}
// A-fragment layout (any M, K=1280):
__device__ __forceinline__ size_t addrA(int m, int k) {
    return ((size_t)((m >> 4) * KB8 + (k >> 3)) << 7)
         + ((m & 7) << 4) + ((k & 3) << 2) + (((k >> 2) & 1) << 1) + ((m >> 3) & 1);
}
// B-fragment layout (weights K x N, K=1280):
__device__ __forceinline__ size_t addrB(int k, int n) {
    return (size_t)((n >> 6) * KB8 + (k >> 3)) * 832
         + (size_t)(k & 7) * 104 + (n & 7) * 12 + ((n >> 3) & 7);
}
__device__ __forceinline__ void cpa16(uint32_t dst, const void* src) {
    asm volatile("cp.async.cg.shared.global [%0], [%1], 16;" :: "r"(dst), "l"(src) : "memory");
}
__device__ __forceinline__ void cpa_commit() {
    asm volatile("cp.async.commit_group;" ::: "memory");
}
__device__ __forceinline__ void cpa_wait2() {
    asm volatile("cp.async.wait_group 2;" ::: "memory");
}
__device__ __forceinline__ uint32_t smem_u32(const void* p) {
    uint32_t a;
    asm("{ .reg .u64 t; cvta.to.shared.u64 t, %1; cvt.u32.u64 %0, t; }" : "=r"(a) : "l"(p));
    return a;
}
__device__ __forceinline__ void mma_tf32(float* d, const uint32_t* a, const uint32_t* b) {
    asm volatile(
        "mma.sync.aligned.m16n8k8.row.col.f32.tf32.tf32.f32 "
        "{%0,%1,%2,%3}, {%4,%5,%6,%7}, {%8,%9}, {%0,%1,%2,%3};"
        : "+f"(d[0]), "+f"(d[1]), "+f"(d[2]), "+f"(d[3])
        : "r"(a[0]), "r"(a[1]), "r"(a[2]), "r"(a[3]),
          "r"(b[0]), "r"(b[1]));
}

// ---------------------------------------------------------------------------
// TF32 mma.sync GEMM with fragment-native smem (all frag loads = LDS.128).
// CTA 128x128, BK=16, 128 thr (4 warps 2x2), warp tile 64x64.
// 4-stage cp.async, 1 barrier/iter, 2 CTAs/SM.
// A: frag layout [M,1280]. B: frag layout [1280,N]. C: fp32 row-major.
// smem/stage: A 2048 w (8KB) + B 3328 w (13KB) = 21504 B.
// ---------------------------------------------------------------------------
#define BM 128
#define BN 128
#define BK 16
#define A_STAGE_W 2048
#define B_STAGE_W 3328
#define ST_W (A_STAGE_W + B_STAGE_W)     // 5376 words
#define NSTAGE 4
#define SMEM_BYTES (NSTAGE * ST_W * 4)   // 86016

__global__ __launch_bounds__(128, 2)
void mma_gemm_frag(const uint32_t* __restrict__ A, const uint32_t* __restrict__ B,
                   float* __restrict__ C, int N)
{
    extern __shared__ char smem[];
    const uint32_t sb = smem_u32(smem);
    uint32_t* smw = (uint32_t*)smem;

    const int tid  = threadIdx.x;
    const int bx   = blockIdx.x, by = blockIdx.y;
    const int warp = tid >> 5, lane = tid & 31;
    const int wm   = warp >> 1, wn = warp & 1;   // 2x2 warp grid
    const int g    = lane >> 2, t = lane & 3;

    // ---- producer: A 4 chunks + B <=7 chunks (16B each) per thread/stage ----
    // A: chunk c = tid + 128*j (j<4); rg = c>>6 (0..7), cc = c&63
    const uint32_t* Asrc[4];
    uint32_t a_dst[4];
    #pragma unroll
    for (int j = 0; j < 4; j++) {
        int c  = tid + 128 * j;
        int rg = c >> 6, cc = c & 63;
        Asrc[j] = A + ((size_t)(by * 8 + rg) * KB8) * 128 + cc * 4;
        a_dst[j] = (uint32_t)c * 16;
    }
    // B: chunk c = tid + 128*j (j<7, c<832); ngl = c>=416, cc = c - ngl*416
    const uint32_t* Bsrc[7];
    uint32_t b_dst[7];
    int nb = 0;
    #pragma unroll
    for (int j = 0; j < 7; j++) {
        int c = tid + 128 * j;
        if (c < 832) {
            int ngl = (c >= 416) ? 1 : 0;
            int cc  = c - ngl * 416;
            Bsrc[nb] = B + (size_t)(bx * 2 + ngl) * KB8 * 832 + cc * 4;
            b_dst[nb] = (uint32_t)(A_STAGE_W * 4) + (uint32_t)c * 16;
            nb++;
        }
    }

    float acc[4][8][4];
    #pragma unroll
    for (int mt = 0; mt < 4; mt++)
        #pragma unroll
        for (int nt = 0; nt < 8; nt++)
            #pragma unroll
            for (int i = 0; i < 4; i++) acc[mt][nt][i] = 0.f;

    const int NIT = KDIM / BK;   // 80

    // ---- prologue: issue stages 0..2 ----
    #pragma unroll
    for (int s = 0; s < NSTAGE - 1; s++) {
        const uint32_t so = sb + s * (ST_W * 4);
        const int kt8 = s * 2;                 // (s*BK)>>3
        #pragma unroll
        for (int j = 0; j < 4; j++)
            cpa16(so + a_dst[j], Asrc[j] + (size_t)kt8 * 128);
        for (int j = 0; j < nb; j++)
            cpa16(so + b_dst[j], Bsrc[j] + (size_t)kt8 * 832);
        cpa_commit();
    }

    int stage = 0;
    for (int i = 0; i < NIT; i++) {
        cpa_wait2();          // group i landed (<=2 groups still in flight)
        __syncthreads();      // visibility + reads of stage (i-1)%4 done

        if (i + NSTAGE - 1 < NIT) {
            int s3 = stage + (NSTAGE - 1);
            if (s3 >= NSTAGE) s3 -= NSTAGE;
            const uint32_t so = sb + s3 * (ST_W * 4);
            const int kt8 = (i + NSTAGE - 1) * 2;
            #pragma unroll
            for (int j = 0; j < 4; j++)
                cpa16(so + a_dst[j], Asrc[j] + (size_t)kt8 * 128);
            for (int j = 0; j < nb; j++)
                cpa16(so + b_dst[j], Bsrc[j] + (size_t)kt8 * 832);
        }
        cpa_commit();

        // ---- compute: 2 k8 steps, all fragment loads are LDS.128 ----
        const uint32_t* As = smw + stage * ST_W;
        const uint32_t* Bs = As + A_STAGE_W;

        #pragma unroll
        for (int ks8 = 0; ks8 < 2; ks8++) {
            uint32_t af[4][4];
            #pragma unroll
            for (int mt = 0; mt < 4; mt++) {
                const uint32_t* p = As + (wm * 4 + mt) * 256 + ks8 * 128
                                       + g * 16 + t * 4;
                *(uint4*)af[mt] = *(const uint4*)p;
            }
            uint32_t bf0[8], bf1[8];
            {
                const uint32_t* p0 = Bs + wn * 1664 + ks8 * 832 + t * 104 + g * 12;
                const uint32_t* p1 = p0 + 4 * 104;   // k = t+4 row
                *(uint4*)&bf0[0] = *(const uint4*)(p0);
                *(uint4*)&bf0[4] = *(const uint4*)(p0 + 4);
                *(uint4*)&bf1[0] = *(const uint4*)(p1);
                *(uint4*)&bf1[4] = *(const uint4*)(p1 + 4);
            }
            #pragma unroll
            for (int mt = 0; mt < 4; mt++)
                #pragma unroll
                for (int nt = 0; nt < 8; nt++) {
                    uint32_t bb[2] = { bf0[nt], bf1[nt] };
                    mma_tf32(acc[mt][nt], af[mt], bb);
                }
        }

        stage = (stage + 1 == NSTAGE) ? 0 : stage + 1;
    }

    // ---- epilogue (row-major C) ----
    #pragma unroll
    for (int mt = 0; mt < 4; mt++) {
        const int row0 = by * BM + wm * 64 + mt * 16 + g;
        #pragma unroll
        for (int nt = 0; nt < 8; nt++) {
            const int col = bx * BN + wn * 64 + nt * 8 + t * 2;
            *(float2*)(C + (size_t)row0 * N + col) =
                make_float2(acc[mt][nt][0], acc[mt][nt][1]);
            *(float2*)(C + (size_t)(row0 + 8) * N + col) =
                make_float2(acc[mt][nt][2], acc[mt][nt][3]);
        }
    }
}

// ---------------------------------------------------------------------------
// x -> gathered rows, tf32, A-fragment layout
// ---------------------------------------------------------------------------
__global__ __launch_bounds__(256)
void cvt_x_gather_kernel(const float* __restrict__ x, uint32_t* __restrict__ xt,
                         const int* __restrict__ win)
{
    int i = blockIdx.x * 256 + threadIdx.x;       // S_TOK*320 threads
    int s  = i / (KDIM / 4);
    int c4 = (i % (KDIM / 4)) * 4;
    float4 v = *(const float4*)(x + (size_t)win[s] * KDIM + c4);
    size_t a0 = addrA(s, c4);                     // +e*4 for e=0..3 (t varies)
    xt[a0 +  0] = f2tf(v.x);
    xt[a0 +  4] = f2tf(v.y);
    xt[a0 +  8] = f2tf(v.z);
    xt[a0 + 12] = f2tf(v.w);
}

// ---------------------------------------------------------------------------
// W[K,N] fp32 row-major -> tf32 B-fragment layout
// ---------------------------------------------------------------------------
__global__ __launch_bounds__(256)
void cvt_w_frag_kernel(const float* __restrict__ W, uint32_t* __restrict__ WF, int N)
{
    int i = blockIdx.x * 256 + threadIdx.x;       // KDIM*(N/4) threads
    int k  = i / (N / 4);
    int n4 = (i % (N / 4)) * 4;
    float4 v = *(const float4*)(W + (size_t)k * N + n4);
    WF[addrB(k, n4 + 0)] = f2tf(v.x);
    WF[addrB(k, n4 + 1)] = f2tf(v.y);
    WF[addrB(k, n4 + 2)] = f2tf(v.z);
    WF[addrB(k, n4 + 3)] = f2tf(v.w);
}

// ---------------------------------------------------------------------------
// Windowed attention, RoPE fused; scatters y (tf32) into A-frag layout,
// rows in ORIGINAL token order (feeds GEMM2 directly).
// ---------------------------------------------------------------------------
__global__ __launch_bounds__(256)
void attn_kernel(const float* __restrict__ qkv, uint32_t* __restrict__ y,
                 const int* __restrict__ win,
                 const float* __restrict__ cosp, const float* __restrict__ sinp)
{
    const int b = blockIdx.x >> 4;
    const int h = blockIdx.x & 15;

    __shared__ float qs[BLK][D_HEAD + 1];
    __shared__ float ks[BLK][D_HEAD + 1];
    __shared__ float vs[BLK][D_HEAD + 1];
    __shared__ float att[BLK][BLK + 1];
    __shared__ int   toks[BLK];

    const int tid = threadIdx.x;
    if (tid < BLK) toks[tid] = win[b * BLK + tid];
    __syncthreads();

    for (int tdx = tid; tdx < BLK * D_HEAD; tdx += 256) {
        int i = tdx / D_HEAD, d = tdx % D_HEAD;
        size_t base = (size_t)(b * BLK + i) * C3 + (size_t)h * D_HEAD + d;
        float q = qkv[base];
        float k = qkv[base + C_DIM];
        float v = qkv[base + 2 * C_DIM];
        int tok = toks[i];
        float cv = cosp[(size_t)tok * D_HEAD + d];
        float sv = sinp[(size_t)tok * D_HEAD + d];
        qs[i][d] = q * cv + k * sv;
        ks[i][d] = k * cv - q * sv;
        vs[i][d] = v;
    }
    __syncthreads();

    {
        int i = tid >> 4, j = tid & 15;
        float sc = 0.f;
        #pragma unroll
        for (int d = 0; d < D_HEAD; d++) sc += qs[i][d] * ks[j][d];
        att[i][j] = sc * 0.11180339887498949f;   // 1/sqrt(80)
    }
    __syncthreads();

    if (tid < BLK) {
        float m = -1e30f;
        #pragma unroll
        for (int j = 0; j < BLK; j++) m = fmaxf(m, att[tid][j]);
        float sum = 0.f;
        #pragma unroll
        for (int j = 0; j < BLK; j++) {
            float e = __expf(att[tid][j] - m);
            att[tid][j] = e;
            sum += e;
        }
        float inv = 1.f / sum;
        #pragma unroll
        for (int j = 0; j < BLK; j++) att[tid][j] *= inv;
    }
    __syncthreads();

    for (int tdx = tid; tdx < BLK * D_HEAD; tdx += 256) {
        int i = tdx / D_HEAD, d = tdx % D_HEAD;
        float a = 0.f;
        #pragma unroll
        for (int j = 0; j < BLK; j++) a += att[i][j] * vs[j][d];
        y[addrA(toks[i], h * D_HEAD + d)] = f2tf(a);
    }
}

// ---------------------------------------------------------------------------
extern "C" void kernel_launch(void* const* d_in, const int* in_sizes, int n_in,
                              void* d_out, int out_size)
{
    const float* x     = (const float*)d_in[0];
    const float* cosp  = (const float*)d_in[1];
    const float* sinp  = (const float*)d_in[2];
    const float* Wqkv  = (const float*)d_in[3];
    const float* Wproj = (const float*)d_in[4];
    const int*   win   = (const int*)  d_in[5];
    float* out = (float*)d_out;

    float *qkv_ptr;
    uint32_t *xt_ptr, *y_ptr, *wqkv_ptr, *wproj_ptr;
    cudaGetSymbolAddress((void**)&qkv_ptr,   g_qkv);
    cudaGetSymbolAddress((void**)&xt_ptr,    g_xt);
    cudaGetSymbolAddress((void**)&y_ptr,     g_y);
    cudaGetSymbolAddress((void**)&wqkv_ptr,  g_wqkvF);
    cudaGetSymbolAddress((void**)&wproj_ptr, g_wprojF);

    cudaFuncSetAttribute(mma_gemm_frag,
        cudaFuncAttributeMaxDynamicSharedMemorySize, SMEM_BYTES);

    // 0) pre-permute inputs: x (gather + tf32 + A-frag), weights (tf32 + B-frag)
    cvt_x_gather_kernel<<<(S_TOK * (KDIM / 4)) / 256, 256>>>(x, xt_ptr, win);
    cvt_w_frag_kernel<<<(KDIM * (C3 / 4)) / 256, 256>>>(Wqkv, wqkv_ptr, C3);
    cvt_w_frag_kernel<<<(KDIM * (C_DIM / 4)) / 256, 256>>>(Wproj, wproj_ptr, C_DIM);

    // 1) QKV GEMM: g_qkv = g_xt @ W_qkv   (gather already applied)
    {
        dim3 grid(C3 / BN, S_TOK / BM);   // 30 x 128
        mma_gemm_frag<<<grid, 128, SMEM_BYTES>>>(xt_ptr, wqkv_ptr, qkv_ptr, C3);
    }

    // 2) Windowed attention (RoPE fused) -> g_y (A-frag layout, original order)
    attn_kernel<<<NBLK * 16, 256>>>(qkv_ptr, y_ptr, win, cosp, sinp);

    // 3) Output projection: out = g_y @ W_proj
    {
        dim3 grid(C_DIM / BN, S_TOK / BM);  // 10 x 128
        mma_gemm_frag<<<grid, 128, SMEM_BYTES>>>(y_ptr, wproj_ptr, out, C_DIM);
    }
}